// round 1
// baseline (speedup 1.0000x reference)
#include <cuda_runtime.h>

// Scratch (no device allocation allowed -> __device__ globals)
__device__ float g_beta[64 * 2];   // per-batch channel max      [B, C]
__device__ float g_M[2 * 64];      // fused weights W1@W2        [C, D2]
__device__ float g_c[64 * 64];     // per-batch fused bias       [B, D2]

static const int B_ = 64;
static const int N_ = 32768;
static const int D2_ = 64;

// -------- Kernel 1: per-batch max over N points (C=2, interleaved) --------
__global__ void max_kernel(const float2* __restrict__ x) {
    const int b = blockIdx.x;
    const float2* xb = x + (long long)b * N_;
    const float NEG_INF = __int_as_float(0xff800000);
    float m0 = NEG_INF, m1 = NEG_INF;
    for (int i = threadIdx.x; i < N_; i += blockDim.x) {
        float2 v = __ldg(&xb[i]);
        m0 = fmaxf(m0, v.x);
        m1 = fmaxf(m1, v.y);
    }
    // warp reduce
    #pragma unroll
    for (int o = 16; o > 0; o >>= 1) {
        m0 = fmaxf(m0, __shfl_xor_sync(0xffffffffu, m0, o));
        m1 = fmaxf(m1, __shfl_xor_sync(0xffffffffu, m1, o));
    }
    __shared__ float s0[32], s1[32];
    const int lane = threadIdx.x & 31;
    const int w    = threadIdx.x >> 5;
    if (lane == 0) { s0[w] = m0; s1[w] = m1; }
    __syncthreads();
    if (w == 0) {
        const int nw = blockDim.x >> 5;
        m0 = (lane < nw) ? s0[lane] : NEG_INF;
        m1 = (lane < nw) ? s1[lane] : NEG_INF;
        #pragma unroll
        for (int o = 16; o > 0; o >>= 1) {
            m0 = fmaxf(m0, __shfl_xor_sync(0xffffffffu, m0, o));
            m1 = fmaxf(m1, __shfl_xor_sync(0xffffffffu, m1, o));
        }
        if (lane == 0) { g_beta[b * 2 + 0] = m0; g_beta[b * 2 + 1] = m1; }
    }
}

// -------- Kernel 2: M = W1@W2 ; c[b,:] = (b1 - beta_b@G1)@W2 + b2 --------
// blocks 0..63: c row b (64 threads, one per output column d)
// block 64    : M rows (64 threads, each computes M[0][d], M[1][d])
__global__ void prep_kernel(const float* __restrict__ W1,
                            const float* __restrict__ b1,
                            const float* __restrict__ G1,
                            const float* __restrict__ W2,
                            const float* __restrict__ b2) {
    const int d = threadIdx.x;   // 0..63
    const int bb = blockIdx.x;
    if (bb < 64) {
        const float beta0 = g_beta[bb * 2 + 0];
        const float beta1 = g_beta[bb * 2 + 1];
        float acc = b2[d];
        #pragma unroll
        for (int k = 0; k < 32; k++) {
            // G1 is [C=2, D1=32] row-major
            const float w = b1[k] - beta0 * G1[k] - beta1 * G1[32 + k];
            acc = fmaf(w, W2[k * 64 + d], acc);
        }
        g_c[bb * 64 + d] = acc;
    } else {
        float a0 = 0.f, a1 = 0.f;
        #pragma unroll
        for (int k = 0; k < 32; k++) {
            const float w2kd = W2[k * 64 + d];
            a0 = fmaf(W1[k],      w2kd, a0);   // W1[0,k]
            a1 = fmaf(W1[32 + k], w2kd, a1);   // W1[1,k]
        }
        g_M[d]      = a0;
        g_M[64 + d] = a1;
    }
}

// -------- Kernel 3: streaming epilogue: out[p, :] = x[p,:]@M + c[b,:] --------
// One block = 16 points = 256 float4 of output (block never crosses a batch
// boundary since N*D2/ (16*64) divides evenly). Thread -> one float4.
__global__ void __launch_bounds__(256) main_kernel(const float2* __restrict__ x,
                                                   float4* __restrict__ out) {
    const int tid = threadIdx.x;
    const int d4  = tid & 15;        // which float4 of the 64-wide row
    const int pl  = tid >> 4;        // point within block (0..15)
    const long long p = (long long)blockIdx.x * 16 + pl;   // global point
    const int b = (int)(p >> 15);    // N = 2^15

    const float2 xv = __ldg(&x[p]);

    const float4 m0 = ((const float4*)g_M)[d4];
    const float4 m1 = ((const float4*)g_M)[16 + d4];
    const float4 cc = ((const float4*)g_c)[b * 16 + d4];

    float4 o;
    o.x = fmaf(xv.x, m0.x, fmaf(xv.y, m1.x, cc.x));
    o.y = fmaf(xv.x, m0.y, fmaf(xv.y, m1.y, cc.y));
    o.z = fmaf(xv.x, m0.z, fmaf(xv.y, m1.z, cc.z));
    o.w = fmaf(xv.x, m0.w, fmaf(xv.y, m1.w, cc.w));

    out[(long long)blockIdx.x * 256 + tid] = o;
}

extern "C" void kernel_launch(void* const* d_in, const int* in_sizes, int n_in,
                              void* d_out, int out_size) {
    const float* pd = (const float*)d_in[0];   // [64, 32768, 2]
    const float* W1 = (const float*)d_in[1];   // [2, 32]
    const float* b1 = (const float*)d_in[2];   // [32]
    const float* G1 = (const float*)d_in[3];   // [2, 32]
    const float* W2 = (const float*)d_in[4];   // [32, 64]
    const float* b2 = (const float*)d_in[5];   // [64]
    float* out = (float*)d_out;                // [64, 32768, 64]

    max_kernel<<<B_, 512>>>((const float2*)pd);
    prep_kernel<<<B_ + 1, 64>>>(W1, b1, G1, W2, b2);

    const int blocks = B_ * N_ / 16;           // 131072
    main_kernel<<<blocks, 256>>>((const float2*)pd, (float4*)out);
}

// round 2
// speedup vs baseline: 1.3883x; 1.3883x over previous
#include <cuda_runtime.h>

// Scratch (no device allocation allowed -> __device__ globals)
__device__ float g_part[1024 * 2]; // partial maxes [B*16, C]
__device__ float g_M[2 * 64];      // fused weights W1@W2        [C, D2]
__device__ float g_c[64 * 64];     // per-batch fused bias       [B, D2]

static const int B_ = 64;
static const int N_ = 32768;
static const int CHUNKS_PER_B = 16;     // max_kernel blocks per batch

// -------- Kernel 1: partial per-batch max over N points (C=2) --------
// 1024 blocks x 256 threads. Each block reduces 2048 float2 (16KB) with
// float4 loads; partial result to g_part[block].
__global__ void __launch_bounds__(256) max_kernel(const float4* __restrict__ x) {
    // x viewed as float4 = 2 points: (p0.x, p0.y, p1.x, p1.y)
    const int blk = blockIdx.x;                 // 0..1023
    const long long base = (long long)blk * 1024;   // float4 index
    const float NEG_INF = __int_as_float(0xff800000);
    float m0 = NEG_INF, m1 = NEG_INF;
    #pragma unroll
    for (int j = 0; j < 4; j++) {
        float4 v = __ldg(&x[base + j * 256 + threadIdx.x]);
        m0 = fmaxf(m0, fmaxf(v.x, v.z));
        m1 = fmaxf(m1, fmaxf(v.y, v.w));
    }
    #pragma unroll
    for (int o = 16; o > 0; o >>= 1) {
        m0 = fmaxf(m0, __shfl_xor_sync(0xffffffffu, m0, o));
        m1 = fmaxf(m1, __shfl_xor_sync(0xffffffffu, m1, o));
    }
    __shared__ float s0[8], s1[8];
    const int lane = threadIdx.x & 31;
    const int w    = threadIdx.x >> 5;
    if (lane == 0) { s0[w] = m0; s1[w] = m1; }
    __syncthreads();
    if (w == 0 && lane < 8) {
        m0 = s0[lane];
        m1 = s1[lane];
        #pragma unroll
        for (int o = 4; o > 0; o >>= 1) {
            m0 = fmaxf(m0, __shfl_xor_sync(0xffu, m0, o));
            m1 = fmaxf(m1, __shfl_xor_sync(0xffu, m1, o));
        }
        if (lane == 0) { g_part[blk * 2 + 0] = m0; g_part[blk * 2 + 1] = m1; }
    }
}

// -------- Kernel 2: final max reduce + M = W1@W2 ; c = (b1 - beta@G1)@W2 + b2
// blocks 0..63: c row b (64 threads, one per output column d)
// block 64    : M rows (64 threads, each computes M[0][d], M[1][d])
__global__ void prep_kernel(const float* __restrict__ W1,
                            const float* __restrict__ b1,
                            const float* __restrict__ G1,
                            const float* __restrict__ W2,
                            const float* __restrict__ b2) {
    const int d = threadIdx.x;   // 0..63
    const int bb = blockIdx.x;
    if (bb < 64) {
        float beta0 = __int_as_float(0xff800000);
        float beta1 = beta0;
        #pragma unroll
        for (int j = 0; j < CHUNKS_PER_B; j++) {
            beta0 = fmaxf(beta0, g_part[(bb * CHUNKS_PER_B + j) * 2 + 0]);
            beta1 = fmaxf(beta1, g_part[(bb * CHUNKS_PER_B + j) * 2 + 1]);
        }
        float acc = b2[d];
        #pragma unroll
        for (int k = 0; k < 32; k++) {
            // G1 is [C=2, D1=32] row-major
            const float w = b1[k] - beta0 * G1[k] - beta1 * G1[32 + k];
            acc = fmaf(w, W2[k * 64 + d], acc);
        }
        g_c[bb * 64 + d] = acc;
    } else {
        float a0 = 0.f, a1 = 0.f;
        #pragma unroll
        for (int k = 0; k < 32; k++) {
            const float w2kd = W2[k * 64 + d];
            a0 = fmaf(W1[k],      w2kd, a0);   // W1[0,k]
            a1 = fmaf(W1[32 + k], w2kd, a1);   // W1[1,k]
        }
        g_M[d]      = a0;
        g_M[64 + d] = a1;
    }
}

// -------- Kernel 3: streaming epilogue: out[p, :] = x[p,:]@M + c[b,:] --------
// 8192 blocks x 256 threads; each block covers 64 points (all in one batch
// since 64 | 32768), each thread writes 4 float4 (one per point group).
// d4 = tid&15 and batch b are block/thread constants -> weights hoisted to regs.
__global__ void __launch_bounds__(256) main_kernel(const float2* __restrict__ x,
                                                   float4* __restrict__ out) {
    const int tid = threadIdx.x;
    const int d4  = tid & 15;        // which float4 of the 64-wide row (fixed)
    const int pl  = tid >> 4;        // point within group (0..15)
    const int b   = blockIdx.x >> 9; // 512 blocks per batch

    const float4 m0 = ((const float4*)g_M)[d4];
    const float4 m1 = ((const float4*)g_M)[16 + d4];
    const float4 cc = ((const float4*)g_c)[b * 16 + d4];

    const long long p0   = (long long)blockIdx.x * 64 + pl;   // global point
    const long long obase = (long long)blockIdx.x * 1024 + tid;

    float2 xv[4];
    #pragma unroll
    for (int j = 0; j < 4; j++)
        xv[j] = __ldg(&x[p0 + j * 16]);

    #pragma unroll
    for (int j = 0; j < 4; j++) {
        float4 o;
        o.x = fmaf(xv[j].x, m0.x, fmaf(xv[j].y, m1.x, cc.x));
        o.y = fmaf(xv[j].x, m0.y, fmaf(xv[j].y, m1.y, cc.y));
        o.z = fmaf(xv[j].x, m0.z, fmaf(xv[j].y, m1.z, cc.z));
        o.w = fmaf(xv[j].x, m0.w, fmaf(xv[j].y, m1.w, cc.w));
        out[obase + j * 256] = o;
    }
}

extern "C" void kernel_launch(void* const* d_in, const int* in_sizes, int n_in,
                              void* d_out, int out_size) {
    const float* pd = (const float*)d_in[0];   // [64, 32768, 2]
    const float* W1 = (const float*)d_in[1];   // [2, 32]
    const float* b1 = (const float*)d_in[2];   // [32]
    const float* G1 = (const float*)d_in[3];   // [2, 32]
    const float* W2 = (const float*)d_in[4];   // [32, 64]
    const float* b2 = (const float*)d_in[5];   // [64]
    float* out = (float*)d_out;                // [64, 32768, 64]

    max_kernel<<<B_ * CHUNKS_PER_B, 256>>>((const float4*)pd);
    prep_kernel<<<B_ + 1, 64>>>(W1, b1, G1, W2, b2);

    const int blocks = B_ * N_ / 64;           // 32768 blocks? no: 64 points/block -> 32768
    main_kernel<<<blocks, 256>>>((const float2*)pd, (float4*)out);
}

// round 3
// speedup vs baseline: 1.5858x; 1.1422x over previous
#include <cuda_runtime.h>

// Scratch (no device allocation allowed -> __device__ globals)
__device__ float g_part[512 * 2];  // partial maxes [B*8, C]
__device__ float g_M[2 * 64];      // fused weights W1@W2        [C, D2]
__device__ float g_c[64 * 64];     // per-batch fused bias       [B, D2]

static const int B_ = 64;
static const int N_ = 32768;
static const int CHUNKS_PER_B = 8;      // max_kernel blocks per batch (512 total)

// -------- Kernel 1: partial per-batch max over N points (C=2) --------
// 512 blocks x 256 threads. Each block reduces 4096 points (32KB) with 8
// independent float4 loads per thread; partial result to g_part[block].
__global__ void __launch_bounds__(256) max_kernel(const float4* __restrict__ x) {
    // x viewed as float4 = 2 points: (p0.x, p0.y, p1.x, p1.y)
    const int blk = blockIdx.x;                    // 0..511
    const long long base = (long long)blk * 2048;  // float4 index
    const float NEG_INF = __int_as_float(0xff800000);
    float a0 = NEG_INF, a1 = NEG_INF, b0 = NEG_INF, b1v = NEG_INF;
    float4 v[8];
    #pragma unroll
    for (int j = 0; j < 8; j++)
        v[j] = __ldg(&x[base + j * 256 + threadIdx.x]);
    #pragma unroll
    for (int j = 0; j < 8; j += 2) {
        a0  = fmaxf(a0,  fmaxf(v[j].x,     v[j].z));
        a1  = fmaxf(a1,  fmaxf(v[j].y,     v[j].w));
        b0  = fmaxf(b0,  fmaxf(v[j + 1].x, v[j + 1].z));
        b1v = fmaxf(b1v, fmaxf(v[j + 1].y, v[j + 1].w));
    }
    float m0 = fmaxf(a0, b0), m1 = fmaxf(a1, b1v);
    #pragma unroll
    for (int o = 16; o > 0; o >>= 1) {
        m0 = fmaxf(m0, __shfl_xor_sync(0xffffffffu, m0, o));
        m1 = fmaxf(m1, __shfl_xor_sync(0xffffffffu, m1, o));
    }
    __shared__ float s0[8], s1[8];
    const int lane = threadIdx.x & 31;
    const int w    = threadIdx.x >> 5;
    if (lane == 0) { s0[w] = m0; s1[w] = m1; }
    __syncthreads();
    if (w == 0 && lane < 8) {
        m0 = s0[lane];
        m1 = s1[lane];
        #pragma unroll
        for (int o = 4; o > 0; o >>= 1) {
            m0 = fmaxf(m0, __shfl_xor_sync(0xffu, m0, o));
            m1 = fmaxf(m1, __shfl_xor_sync(0xffu, m1, o));
        }
        if (lane == 0) { g_part[blk * 2 + 0] = m0; g_part[blk * 2 + 1] = m1; }
    }
}

// -------- Kernel 2: final max reduce + M = W1@W2 ; c = (b1 - beta@G1)@W2 + b2
// blocks 0..63: c row b (64 threads, one per output column d)
// block 64    : M rows (64 threads, each computes M[0][d], M[1][d])
__global__ void prep_kernel(const float* __restrict__ W1,
                            const float* __restrict__ b1,
                            const float* __restrict__ G1,
                            const float* __restrict__ W2,
                            const float* __restrict__ b2) {
    const int d = threadIdx.x;   // 0..63
    const int bb = blockIdx.x;
    if (bb < 64) {
        float beta0 = __int_as_float(0xff800000);
        float beta1 = beta0;
        #pragma unroll
        for (int j = 0; j < CHUNKS_PER_B; j++) {
            beta0 = fmaxf(beta0, g_part[(bb * CHUNKS_PER_B + j) * 2 + 0]);
            beta1 = fmaxf(beta1, g_part[(bb * CHUNKS_PER_B + j) * 2 + 1]);
        }
        float acc = b2[d];
        #pragma unroll
        for (int k = 0; k < 32; k++) {
            // G1 is [C=2, D1=32] row-major
            const float w = b1[k] - beta0 * G1[k] - beta1 * G1[32 + k];
            acc = fmaf(w, W2[k * 64 + d], acc);
        }
        g_c[bb * 64 + d] = acc;
    } else {
        float a0 = 0.f, a1 = 0.f;
        #pragma unroll
        for (int k = 0; k < 32; k++) {
            const float w2kd = W2[k * 64 + d];
            a0 = fmaf(W1[k],      w2kd, a0);   // W1[0,k]
            a1 = fmaf(W1[32 + k], w2kd, a1);   // W1[1,k]
        }
        g_M[d]      = a0;
        g_M[64 + d] = a1;
    }
}

// -------- Kernel 3: streaming epilogue: out[p, :] = x[p,:]@M + c[b,:] --------
// 32768 blocks x 256 threads; each block covers 64 points (all in one batch
// since 64 | 32768), each thread writes 4 float4 with streaming (evict-first)
// stores: the output is never re-read, so don't allocate it in L2.
__global__ void __launch_bounds__(256) main_kernel(const float2* __restrict__ x,
                                                   float4* __restrict__ out) {
    const int tid = threadIdx.x;
    const int d4  = tid & 15;        // which float4 of the 64-wide row (fixed)
    const int pl  = tid >> 4;        // point within group (0..15)
    const int b   = blockIdx.x >> 9; // 512 blocks per batch

    const float4 m0 = ((const float4*)g_M)[d4];
    const float4 m1 = ((const float4*)g_M)[16 + d4];
    const float4 cc = ((const float4*)g_c)[b * 16 + d4];

    const long long p0    = (long long)blockIdx.x * 64 + pl;   // global point
    const long long obase = (long long)blockIdx.x * 1024 + tid;

    float2 xv[4];
    #pragma unroll
    for (int j = 0; j < 4; j++)
        xv[j] = __ldg(&x[p0 + j * 16]);

    #pragma unroll
    for (int j = 0; j < 4; j++) {
        float4 o;
        o.x = fmaf(xv[j].x, m0.x, fmaf(xv[j].y, m1.x, cc.x));
        o.y = fmaf(xv[j].x, m0.y, fmaf(xv[j].y, m1.y, cc.y));
        o.z = fmaf(xv[j].x, m0.z, fmaf(xv[j].y, m1.z, cc.z));
        o.w = fmaf(xv[j].x, m0.w, fmaf(xv[j].y, m1.w, cc.w));
        __stcs(&out[obase + j * 256], o);
    }
}

extern "C" void kernel_launch(void* const* d_in, const int* in_sizes, int n_in,
                              void* d_out, int out_size) {
    const float* pd = (const float*)d_in[0];   // [64, 32768, 2]
    const float* W1 = (const float*)d_in[1];   // [2, 32]
    const float* b1 = (const float*)d_in[2];   // [32]
    const float* G1 = (const float*)d_in[3];   // [2, 32]
    const float* W2 = (const float*)d_in[4];   // [32, 64]
    const float* b2 = (const float*)d_in[5];   // [64]
    float* out = (float*)d_out;                // [64, 32768, 64]

    max_kernel<<<B_ * CHUNKS_PER_B, 256>>>((const float4*)pd);
    prep_kernel<<<B_ + 1, 64>>>(W1, b1, G1, W2, b2);

    const int blocks = B_ * N_ / 64;           // 32768 blocks, 64 points each
    main_kernel<<<blocks, 256>>>((const float2*)pd, (float4*)out);
}